// round 1
// baseline (speedup 1.0000x reference)
#include <cuda_runtime.h>
#include <math.h>

#define B_   2
#define T_   2048
#define C_   1024
#define NH_  16
#define HS_  64
#define WIN_ 256

// Scratch (allocation-free rule: __device__ globals)
__device__ float g_qkv[(size_t)B_ * T_ * 3 * C_];   // [B,T,3C]
__device__ float g_y  [(size_t)B_ * T_ * C_];       // [B,T,C]

// ---------------------------------------------------------------------------
// fp32 SGEMM: C[M,N] = A[M,K] @ B[K,N], all row-major.
// 128x128 block tile, BK=16, 256 threads, 8x8 per thread.
// Requires M%128==0, N%128==0, K%16==0 (true for all our shapes).
// ---------------------------------------------------------------------------
__global__ __launch_bounds__(256) void sgemm128(const float* __restrict__ A,
                                                const float* __restrict__ B,
                                                float* __restrict__ Cout,
                                                int M, int N, int K)
{
    __shared__ float As[16][132];   // transposed A tile, padded (stride 132)
    __shared__ float Bs[16][128];

    const int tid  = threadIdx.x;
    const int crow = blockIdx.y * 128;
    const int ccol = blockIdx.x * 128;

    const int ar = tid >> 2;          // 0..63  (A tile row, +64 second pass)
    const int ac = (tid & 3) * 4;     // 0,4,8,12 (A tile col, float4)
    const int br = tid >> 5;          // 0..7   (B tile row, +8 second pass)
    const int bc = (tid & 31) * 4;    // 0..124 (B tile col, float4)

    const int trow = (tid >> 4) * 8;  // 0..120
    const int tcol = (tid & 15) * 8;  // 0..120

    float acc[8][8];
#pragma unroll
    for (int m = 0; m < 8; m++)
#pragma unroll
        for (int n = 0; n < 8; n++) acc[m][n] = 0.0f;

    const float* Aptr = A + (size_t)crow * K;
    const float* Bptr = B + ccol;

    for (int k0 = 0; k0 < K; k0 += 16) {
#pragma unroll
        for (int p = 0; p < 2; p++) {
            const float4 v = *reinterpret_cast<const float4*>(
                Aptr + (size_t)(ar + p * 64) * K + k0 + ac);
            As[ac + 0][ar + p * 64] = v.x;
            As[ac + 1][ar + p * 64] = v.y;
            As[ac + 2][ar + p * 64] = v.z;
            As[ac + 3][ar + p * 64] = v.w;
        }
#pragma unroll
        for (int p = 0; p < 2; p++) {
            const float4 v = *reinterpret_cast<const float4*>(
                Bptr + (size_t)(k0 + br + p * 8) * N + bc);
            *reinterpret_cast<float4*>(&Bs[br + p * 8][bc]) = v;
        }
        __syncthreads();

#pragma unroll
        for (int kk = 0; kk < 16; kk++) {
            float ra[8], rb[8];
#pragma unroll
            for (int m = 0; m < 8; m++) ra[m] = As[kk][trow + m];
#pragma unroll
            for (int n = 0; n < 8; n++) rb[n] = Bs[kk][tcol + n];
#pragma unroll
            for (int m = 0; m < 8; m++)
#pragma unroll
                for (int n = 0; n < 8; n++) acc[m][n] += ra[m] * rb[n];
        }
        __syncthreads();
    }

#pragma unroll
    for (int m = 0; m < 8; m++) {
        float* Crow = Cout + (size_t)(crow + trow + m) * N + ccol + tcol;
#pragma unroll
        for (int n = 0; n < 8; n += 4) {
            *reinterpret_cast<float4*>(Crow + n) =
                make_float4(acc[m][n], acc[m][n + 1], acc[m][n + 2], acc[m][n + 3]);
        }
    }
}

// ---------------------------------------------------------------------------
// Fused sliding-window flash attention (fp32).
// One block = (batch b, head h, 64-query tile qt). 256 threads (16x16),
// each thread owns a 4x4 tile of S and of O. Key tiles of 64 iterate over
// the window [qt-4 .. qt].
// Smem: Qs (d-major, stride 68), KPs (K d-major / reused as P row-major,
// stride 68), Vs (natural, stride 64). 51200 bytes dynamic.
// ---------------------------------------------------------------------------
#define QS_STRIDE 68
#define SWA_SMEM_BYTES ((64 * QS_STRIDE * 2 + 64 * 64) * 4)

__global__ __launch_bounds__(256) void swa_kernel(const float* __restrict__ qkv,
                                                  float* __restrict__ y)
{
    extern __shared__ float sm[];
    float* Qs  = sm;                  // [64 d][68] : Qs[d*68 + i]
    float* KPs = Qs + 64 * QS_STRIDE; // Ks[d*68 + j]  then reused as Ps[i*68 + j]
    float* Vs  = KPs + 64 * QS_STRIDE;// [64 j][64 d]

    const int qt  = blockIdx.x;   // 0..31
    const int h   = blockIdx.y;   // 0..15
    const int b   = blockIdx.z;   // 0..1
    const int tid = threadIdx.x;
    const int i0  = (tid >> 4) * 4;   // query rows this thread owns
    const int j0  = (tid & 15) * 4;   // key cols / head-dim cols this thread owns

    const size_t stride_t = 3 * C_;
    const float* qbase = qkv + (size_t)b * T_ * stride_t + (size_t)h * HS_;

    // Load Q tile transposed into Qs[d][i]
    for (int it = tid; it < 64 * 16; it += 256) {
        const int r  = it >> 4;
        const int c4 = (it & 15) << 2;
        const float4 v = *reinterpret_cast<const float4*>(
            qbase + (size_t)(qt * 64 + r) * stride_t + c4);
        Qs[(c4 + 0) * QS_STRIDE + r] = v.x;
        Qs[(c4 + 1) * QS_STRIDE + r] = v.y;
        Qs[(c4 + 2) * QS_STRIDE + r] = v.z;
        Qs[(c4 + 3) * QS_STRIDE + r] = v.w;
    }

    float o[4][4];
    float mrow[4], lrow[4];
#pragma unroll
    for (int m = 0; m < 4; m++) {
        mrow[m] = -1e30f;
        lrow[m] = 0.0f;
#pragma unroll
        for (int n = 0; n < 4; n++) o[m][n] = 0.0f;
    }

    const int lo    = qt * 64 - (WIN_ - 1);
    const int kt_lo = lo > 0 ? (lo >> 6) : 0;

    for (int kt = kt_lo; kt <= qt; kt++) {
        __syncthreads();   // previous tile fully consumed before overwrite
        // Load K (transposed, d-major) and V (natural)
        for (int it = tid; it < 64 * 16; it += 256) {
            const int r  = it >> 4;
            const int c4 = (it & 15) << 2;
            const float* kp = qbase + C_ + (size_t)(kt * 64 + r) * stride_t + c4;
            const float4 kv = *reinterpret_cast<const float4*>(kp);
            KPs[(c4 + 0) * QS_STRIDE + r] = kv.x;
            KPs[(c4 + 1) * QS_STRIDE + r] = kv.y;
            KPs[(c4 + 2) * QS_STRIDE + r] = kv.z;
            KPs[(c4 + 3) * QS_STRIDE + r] = kv.w;
            const float4 vv = *reinterpret_cast<const float4*>(kp + C_);
            *reinterpret_cast<float4*>(&Vs[r * 64 + c4]) = vv;
        }
        __syncthreads();

        // S = Q @ K^T (4x4 per thread)
        float s[4][4];
#pragma unroll
        for (int m = 0; m < 4; m++)
#pragma unroll
            for (int n = 0; n < 4; n++) s[m][n] = 0.0f;

#pragma unroll 8
        for (int d = 0; d < 64; d++) {
            float ra[4], rb[4];
#pragma unroll
            for (int m = 0; m < 4; m++) ra[m] = Qs[d * QS_STRIDE + i0 + m];
#pragma unroll
            for (int n = 0; n < 4; n++) rb[n] = KPs[d * QS_STRIDE + j0 + n];
#pragma unroll
            for (int m = 0; m < 4; m++)
#pragma unroll
                for (int n = 0; n < 4; n++) s[m][n] += ra[m] * rb[n];
        }

        // Scale + mask, per-row max over the 16-lane row group
        const float sc = 0.125f;  // 1/sqrt(64)
        float tmax[4];
#pragma unroll
        for (int m = 0; m < 4; m++) {
            tmax[m] = -1e30f;
            const int ig = qt * 64 + i0 + m;
#pragma unroll
            for (int n = 0; n < 4; n++) {
                const int jg = kt * 64 + j0 + n;
                const bool valid = (jg <= ig) && (ig - jg < WIN_);
                s[m][n] = valid ? s[m][n] * sc : -1e30f;
                if (valid) tmax[m] = fmaxf(tmax[m], s[m][n]);
            }
#pragma unroll
            for (int off = 8; off > 0; off >>= 1)
                tmax[m] = fmaxf(tmax[m], __shfl_xor_sync(0xffffffffu, tmax[m], off));
        }

        // Online softmax update
        float p[4][4], escale[4];
#pragma unroll
        for (int m = 0; m < 4; m++) {
            const float mnew = fmaxf(mrow[m], tmax[m]);
            escale[m] = __expf(mrow[m] - mnew);
            float psum = 0.0f;
            const int ig = qt * 64 + i0 + m;
#pragma unroll
            for (int n = 0; n < 4; n++) {
                const int jg = kt * 64 + j0 + n;
                const bool valid = (jg <= ig) && (ig - jg < WIN_);
                p[m][n] = valid ? __expf(s[m][n] - mnew) : 0.0f;
                psum += p[m][n];
            }
#pragma unroll
            for (int off = 8; off > 0; off >>= 1)
                psum += __shfl_xor_sync(0xffffffffu, psum, off);
            lrow[m] = lrow[m] * escale[m] + psum;
            mrow[m] = mnew;
#pragma unroll
            for (int n = 0; n < 4; n++) o[m][n] *= escale[m];
        }

        __syncthreads();   // all lanes done reading Ks before P overwrites it
        // Stage P into the (former K) buffer, row-major stride 68
#pragma unroll
        for (int m = 0; m < 4; m++)
            *reinterpret_cast<float4*>(&KPs[(i0 + m) * QS_STRIDE + j0]) =
                make_float4(p[m][0], p[m][1], p[m][2], p[m][3]);
        __syncthreads();

        // O += P @ V
#pragma unroll 8
        for (int j = 0; j < 64; j++) {
            float ra[4];
#pragma unroll
            for (int m = 0; m < 4; m++) ra[m] = KPs[(i0 + m) * QS_STRIDE + j];
            const float4 rv = *reinterpret_cast<const float4*>(&Vs[j * 64 + j0]);
            const float rb[4] = {rv.x, rv.y, rv.z, rv.w};
#pragma unroll
            for (int m = 0; m < 4; m++)
#pragma unroll
                for (int n = 0; n < 4; n++) o[m][n] += ra[m] * rb[n];
        }
    }

    // Normalize and write y[b, qt*64+i, h*64+d]
#pragma unroll
    for (int m = 0; m < 4; m++) {
        const float inv = 1.0f / lrow[m];
        float* yp = y + ((size_t)b * T_ + qt * 64 + i0 + m) * C_ + h * HS_ + j0;
        *reinterpret_cast<float4*>(yp) =
            make_float4(o[m][0] * inv, o[m][1] * inv, o[m][2] * inv, o[m][3] * inv);
    }
}

// ---------------------------------------------------------------------------
extern "C" void kernel_launch(void* const* d_in, const int* in_sizes, int n_in,
                              void* d_out, int out_size)
{
    const float* x      = (const float*)d_in[0];
    const float* W_attn = (const float*)d_in[1];
    const float* W_proj = (const float*)d_in[2];
    float* out = (float*)d_out;

    float* qkv = nullptr;
    float* y   = nullptr;
    cudaGetSymbolAddress((void**)&qkv, g_qkv);
    cudaGetSymbolAddress((void**)&y, g_y);

    // 1) qkv = x @ W_attn   (M=4096, N=3072, K=1024)
    {
        dim3 grid((3 * C_) / 128, (B_ * T_) / 128);
        sgemm128<<<grid, 256>>>(x, W_attn, qkv, B_ * T_, 3 * C_, C_);
    }

    // 2) fused sliding-window attention -> y
    {
        cudaFuncSetAttribute(swa_kernel,
                             cudaFuncAttributeMaxDynamicSharedMemorySize,
                             SWA_SMEM_BYTES);
        dim3 grid(T_ / 64, NH_, B_);
        swa_kernel<<<grid, 256, SWA_SMEM_BYTES>>>(qkv, y);
    }

    // 3) out = y @ W_proj   (M=4096, N=1024, K=1024)
    {
        dim3 grid(C_ / 128, (B_ * T_) / 128);
        sgemm128<<<grid, 256>>>(y, W_proj, out, B_ * T_, C_, C_);
    }
}

// round 3
// speedup vs baseline: 3.1431x; 3.1431x over previous
#include <cuda_runtime.h>
#include <cuda_bf16.h>
#include <cstdint>
#include <math.h>

#define B_   2
#define T_   2048
#define C_   1024
#define NH_  16
#define HS_  64
#define WIN_ 256

// ---------------------------------------------------------------------------
// Scratch (__device__ globals; no allocation allowed)
// ---------------------------------------------------------------------------
__device__ float g_qkv[(size_t)B_ * T_ * 3 * C_];        // [B,T,3C] fp32
__device__ float g_y  [(size_t)B_ * T_ * C_];            // [B,T,C]  fp32
__device__ __nv_bfloat16 g_xh[(size_t)B_ * T_ * C_];
__device__ __nv_bfloat16 g_xl[(size_t)B_ * T_ * C_];
__device__ __nv_bfloat16 g_yh[(size_t)B_ * T_ * C_];
__device__ __nv_bfloat16 g_yl[(size_t)B_ * T_ * C_];
__device__ __nv_bfloat16 g_wah[(size_t)3 * C_ * C_];     // W_attn^T [3C, C]
__device__ __nv_bfloat16 g_wal[(size_t)3 * C_ * C_];
__device__ __nv_bfloat16 g_wph[(size_t)C_ * C_];         // W_proj^T [C, C]
__device__ __nv_bfloat16 g_wpl[(size_t)C_ * C_];

// ---------------------------------------------------------------------------
// mma.sync / ldmatrix / cp.async helpers (plain sm_80-level PTX; no 'a' features)
// ---------------------------------------------------------------------------
__device__ __forceinline__ uint32_t smem_to_u32(const void* smem_ptr) {
    uint32_t addr;
    asm("{ .reg .u64 tmp; cvta.to.shared.u64 tmp, %1; cvt.u32.u64 %0, tmp; }"
        : "=r"(addr) : "l"(smem_ptr));
    return addr;
}
__device__ __forceinline__ void cp16(uint32_t saddr, const void* g) {
    asm volatile("cp.async.cg.shared.global [%0], [%1], 16;" :: "r"(saddr), "l"(g));
}
__device__ __forceinline__ void cp_commit() {
    asm volatile("cp.async.commit_group;" ::: "memory");
}
template <int N>
__device__ __forceinline__ void cp_wait() {
    asm volatile("cp.async.wait_group %0;" :: "n"(N) : "memory");
}
__device__ __forceinline__ void ldm4(uint32_t* r, uint32_t addr) {
    asm volatile("ldmatrix.sync.aligned.m8n8.x4.shared.b16 {%0,%1,%2,%3}, [%4];"
        : "=r"(r[0]), "=r"(r[1]), "=r"(r[2]), "=r"(r[3]) : "r"(addr));
}
__device__ __forceinline__ void mma_bf16(float* c, const uint32_t* a, const uint32_t* b) {
    asm volatile("mma.sync.aligned.m16n8k16.row.col.f32.bf16.bf16.f32 "
        "{%0,%1,%2,%3}, {%4,%5,%6,%7}, {%8,%9}, {%0,%1,%2,%3};"
        : "+f"(c[0]), "+f"(c[1]), "+f"(c[2]), "+f"(c[3])
        : "r"(a[0]), "r"(a[1]), "r"(a[2]), "r"(a[3]), "r"(b[0]), "r"(b[1]));
}

// ---------------------------------------------------------------------------
// Split-precision conversion kernels
// ---------------------------------------------------------------------------
__global__ __launch_bounds__(256) void split_convert(const float* __restrict__ in,
                                                     __nv_bfloat16* __restrict__ oh,
                                                     __nv_bfloat16* __restrict__ ol,
                                                     int n2)
{
    int i = blockIdx.x * blockDim.x + threadIdx.x;
    if (i >= n2) return;
    float2 v = reinterpret_cast<const float2*>(in)[i];
    __nv_bfloat16 hx = __float2bfloat16(v.x);
    __nv_bfloat16 hy = __float2bfloat16(v.y);
    float rx = v.x - __bfloat162float(hx);
    float ry = v.y - __bfloat162float(hy);
    __nv_bfloat162 th; th.x = hx; th.y = hy;
    __nv_bfloat162 tl; tl.x = __float2bfloat16(rx); tl.y = __float2bfloat16(ry);
    reinterpret_cast<__nv_bfloat162*>(oh)[i] = th;
    reinterpret_cast<__nv_bfloat162*>(ol)[i] = tl;
}

// in: [K,N] fp32 row-major -> out hi/lo: [N,K] bf16 (transposed, K-major)
__global__ __launch_bounds__(256) void transpose_split(const float* __restrict__ in,
                                                       __nv_bfloat16* __restrict__ oh,
                                                       __nv_bfloat16* __restrict__ ol,
                                                       int K, int N)
{
    __shared__ float t[32][33];
    const int nt = blockIdx.x * 32;
    const int kt = blockIdx.y * 32;
    const int tx = threadIdx.x & 31;
    const int ty = threadIdx.x >> 5;     // 0..7
#pragma unroll
    for (int j = 0; j < 4; j++) {
        int k = kt + ty + j * 8;
        t[ty + j * 8][tx] = in[(size_t)k * N + nt + tx];
    }
    __syncthreads();
#pragma unroll
    for (int j = 0; j < 4; j++) {
        int n = nt + ty + j * 8;
        int k = kt + tx;
        float v = t[tx][ty + j * 8];
        __nv_bfloat16 h = __float2bfloat16(v);
        oh[(size_t)n * K + k] = h;
        ol[(size_t)n * K + k] = __float2bfloat16(v - __bfloat162float(h));
    }
}

// ---------------------------------------------------------------------------
// Split-bf16 GEMM via mma.sync (HMMA): C[M,N] = (Ah+Al) @ (Bh+Bl)^T
//   A hi/lo: [M,K] bf16 row-major; B hi/lo: [N,K] bf16 row-major (K-major).
// CTA 128x128, BK=32, 256 threads (8 warps: 2M x 4N, warp tile 64x32),
// cp.async double-buffered smem, pad-8 rows (80B stride, conflict-free ldmatrix).
// ---------------------------------------------------------------------------
#define BM 128
#define BN 128
#define BKC 32
#define LDA 40                               // bf16 per smem row (32 + 8 pad)
#define TILE_BYTES (128 * LDA * 2)           // 10240
#define OFF_AH 0
#define OFF_AL (TILE_BYTES)
#define OFF_BH (2 * TILE_BYTES)
#define OFF_BL (3 * TILE_BYTES)
#define STAGE_BYTES (4 * TILE_BYTES)         // 40960
#define GEMM_SMEM (2 * STAGE_BYTES)          // 81920

__global__ __launch_bounds__(256) void gemm_mma(const __nv_bfloat16* __restrict__ Ah,
                                                const __nv_bfloat16* __restrict__ Al,
                                                const __nv_bfloat16* __restrict__ Bh,
                                                const __nv_bfloat16* __restrict__ Bl,
                                                float* __restrict__ C,
                                                int M, int N, int K)
{
    extern __shared__ char smem[];
    const uint32_t sbase = smem_to_u32(smem);

    const int tid  = threadIdx.x;
    const int lane = tid & 31;
    const int wid  = tid >> 5;
    const int warpRow = wid & 1;    // 0..1 (M)
    const int warpCol = wid >> 1;   // 0..3 (N)
    const int m0 = blockIdx.y * BM;
    const int n0 = blockIdx.x * BN;
    const int NC = K / BKC;

    // per-thread global-load mapping: 2 16B vectors per operand tile
    const int v0 = tid, v1 = tid + 256;
    const int r0 = v0 >> 2, s0 = v0 & 3;     // row 0..127, seg 0..3 (8 bf16 each)
    const int r1 = v1 >> 2, s1 = v1 & 3;
    const uint32_t so0 = (uint32_t)(r0 * LDA + s0 * 8) * 2;
    const uint32_t so1 = (uint32_t)(r1 * LDA + s1 * 8) * 2;

    float acc[4][4][4];
#pragma unroll
    for (int mt = 0; mt < 4; mt++)
#pragma unroll
        for (int nt = 0; nt < 4; nt++)
#pragma unroll
            for (int e = 0; e < 4; e++) acc[mt][nt][e] = 0.0f;

    // ldmatrix per-lane address components (byte offsets within a tile)
    const uint32_t a_row = (uint32_t)(warpRow * 64 + (lane & 15));
    const uint32_t a_kof = (uint32_t)((lane >> 4) << 3);           // 0 or 8
    const uint32_t b_row = (uint32_t)(warpCol * 32 + (lane & 7) + ((lane & 16) >> 1));
    const uint32_t b_kof = (uint32_t)(lane & 8);                   // 0 or 8

    auto load_stage = [&](int stg, int kk) {
        const uint32_t sb = sbase + stg * STAGE_BYTES;
        const size_t ga0 = (size_t)(m0 + r0) * K + kk + s0 * 8;
        const size_t ga1 = (size_t)(m0 + r1) * K + kk + s1 * 8;
        const size_t gb0 = (size_t)(n0 + r0) * K + kk + s0 * 8;
        const size_t gb1 = (size_t)(n0 + r1) * K + kk + s1 * 8;
        cp16(sb + OFF_AH + so0, Ah + ga0);
        cp16(sb + OFF_AH + so1, Ah + ga1);
        cp16(sb + OFF_AL + so0, Al + ga0);
        cp16(sb + OFF_AL + so1, Al + ga1);
        cp16(sb + OFF_BH + so0, Bh + gb0);
        cp16(sb + OFF_BH + so1, Bh + gb1);
        cp16(sb + OFF_BL + so0, Bl + gb0);
        cp16(sb + OFF_BL + so1, Bl + gb1);
        cp_commit();
    };

    load_stage(0, 0);

    for (int c = 0; c < NC; c++) {
        const int buf = c & 1;
        if (c + 1 < NC) {
            load_stage(buf ^ 1, (c + 1) * BKC);
            cp_wait<1>();
        } else {
            cp_wait<0>();
        }
        __syncthreads();

        const uint32_t sb = sbase + buf * STAGE_BYTES;

#pragma unroll
        for (int ks = 0; ks < 2; ks++) {
            const uint32_t akc = (uint32_t)(ks * 16) + a_kof;
            const uint32_t bkc = (uint32_t)(ks * 16) + b_kof;

            uint32_t fAh[4][4], fAl[4][4];
#pragma unroll
            for (int mt = 0; mt < 4; mt++) {
                const uint32_t off = ((a_row + mt * 16) * LDA + akc) * 2;
                ldm4(fAh[mt], sb + OFF_AH + off);
                ldm4(fAl[mt], sb + OFF_AL + off);
            }
            uint32_t fBh[2][4], fBl[2][4];
#pragma unroll
            for (int g = 0; g < 2; g++) {
                const uint32_t off = ((b_row + g * 16) * LDA + bkc) * 2;
                ldm4(fBh[g], sb + OFF_BH + off);
                ldm4(fBl[g], sb + OFF_BL + off);
            }

#pragma unroll
            for (int mt = 0; mt < 4; mt++) {
#pragma unroll
                for (int nt = 0; nt < 4; nt++) {
                    const uint32_t* bh = &fBh[nt >> 1][(nt & 1) * 2];
                    const uint32_t* bl = &fBl[nt >> 1][(nt & 1) * 2];
                    mma_bf16(acc[mt][nt], fAh[mt], bh);
                    mma_bf16(acc[mt][nt], fAh[mt], bl);
                    mma_bf16(acc[mt][nt], fAl[mt], bh);
                }
            }
        }
        __syncthreads();
    }

    // epilogue: fragment -> global (float2 stores, 8B aligned)
    const int erow = m0 + warpRow * 64 + (lane >> 2);
    const int ecol = n0 + warpCol * 32 + (lane & 3) * 2;
#pragma unroll
    for (int mt = 0; mt < 4; mt++) {
#pragma unroll
        for (int nt = 0; nt < 4; nt++) {
            float* p0 = C + (size_t)(erow + mt * 16) * N + ecol + nt * 8;
            float* p1 = C + (size_t)(erow + mt * 16 + 8) * N + ecol + nt * 8;
            *reinterpret_cast<float2*>(p0) = make_float2(acc[mt][nt][0], acc[mt][nt][1]);
            *reinterpret_cast<float2*>(p1) = make_float2(acc[mt][nt][2], acc[mt][nt][3]);
        }
    }
}

// ---------------------------------------------------------------------------
// Fused sliding-window flash attention (fp32) — unchanged.
// ---------------------------------------------------------------------------
#define QS_STRIDE 68
#define SWA_SMEM_BYTES ((64 * QS_STRIDE * 2 + 64 * 64) * 4)

__global__ __launch_bounds__(256) void swa_kernel(const float* __restrict__ qkv,
                                                  float* __restrict__ y)
{
    extern __shared__ float sm[];
    float* Qs  = sm;
    float* KPs = Qs + 64 * QS_STRIDE;
    float* Vs  = KPs + 64 * QS_STRIDE;

    const int qt  = blockIdx.x;
    const int h   = blockIdx.y;
    const int b   = blockIdx.z;
    const int tid = threadIdx.x;
    const int i0  = (tid >> 4) * 4;
    const int j0  = (tid & 15) * 4;

    const size_t stride_t = 3 * C_;
    const float* qbase = qkv + (size_t)b * T_ * stride_t + (size_t)h * HS_;

    for (int it = tid; it < 64 * 16; it += 256) {
        const int r  = it >> 4;
        const int c4 = (it & 15) << 2;
        const float4 v = *reinterpret_cast<const float4*>(
            qbase + (size_t)(qt * 64 + r) * stride_t + c4);
        Qs[(c4 + 0) * QS_STRIDE + r] = v.x;
        Qs[(c4 + 1) * QS_STRIDE + r] = v.y;
        Qs[(c4 + 2) * QS_STRIDE + r] = v.z;
        Qs[(c4 + 3) * QS_STRIDE + r] = v.w;
    }

    float o[4][4];
    float mrow[4], lrow[4];
#pragma unroll
    for (int m = 0; m < 4; m++) {
        mrow[m] = -1e30f;
        lrow[m] = 0.0f;
#pragma unroll
        for (int n = 0; n < 4; n++) o[m][n] = 0.0f;
    }

    const int lo    = qt * 64 - (WIN_ - 1);
    const int kt_lo = lo > 0 ? (lo >> 6) : 0;

    for (int kt = kt_lo; kt <= qt; kt++) {
        __syncthreads();
        for (int it = tid; it < 64 * 16; it += 256) {
            const int r  = it >> 4;
            const int c4 = (it & 15) << 2;
            const float* kp = qbase + C_ + (size_t)(kt * 64 + r) * stride_t + c4;
            const float4 kv = *reinterpret_cast<const float4*>(kp);
            KPs[(c4 + 0) * QS_STRIDE + r] = kv.x;
            KPs[(c4 + 1) * QS_STRIDE + r] = kv.y;
            KPs[(c4 + 2) * QS_STRIDE + r] = kv.z;
            KPs[(c4 + 3) * QS_STRIDE + r] = kv.w;
            const float4 vv = *reinterpret_cast<const float4*>(kp + C_);
            *reinterpret_cast<float4*>(&Vs[r * 64 + c4]) = vv;
        }
        __syncthreads();

        float s[4][4];
#pragma unroll
        for (int m = 0; m < 4; m++)
#pragma unroll
            for (int n = 0; n < 4; n++) s[m][n] = 0.0f;

#pragma unroll 8
        for (int d = 0; d < 64; d++) {
            float ra[4], rb[4];
#pragma unroll
            for (int m = 0; m < 4; m++) ra[m] = Qs[d * QS_STRIDE + i0 + m];
#pragma unroll
            for (int n = 0; n < 4; n++) rb[n] = KPs[d * QS_STRIDE + j0 + n];
#pragma unroll
            for (int m = 0; m < 4; m++)
#pragma unroll
                for (int n = 0; n < 4; n++) s[m][n] += ra[m] * rb[n];
        }

        const float sc = 0.125f;
        float tmax[4];
#pragma unroll
        for (int m = 0; m < 4; m++) {
            tmax[m] = -1e30f;
            const int ig = qt * 64 + i0 + m;
#pragma unroll
            for (int n = 0; n < 4; n++) {
                const int jg = kt * 64 + j0 + n;
                const bool valid = (jg <= ig) && (ig - jg < WIN_);
                s[m][n] = valid ? s[m][n] * sc : -1e30f;
                if (valid) tmax[m] = fmaxf(tmax[m], s[m][n]);
            }
#pragma unroll
            for (int off = 8; off > 0; off >>= 1)
                tmax[m] = fmaxf(tmax[m], __shfl_xor_sync(0xffffffffu, tmax[m], off));
        }

        float p[4][4], escale[4];
#pragma unroll
        for (int m = 0; m < 4; m++) {
            const float mnew = fmaxf(mrow[m], tmax[m]);
            escale[m] = __expf(mrow[m] - mnew);
            float psum = 0.0f;
            const int ig = qt * 64 + i0 + m;
#pragma unroll
            for (int n = 0; n < 4; n++) {
                const int jg = kt * 64 + j0 + n;
                const bool valid = (jg <= ig) && (ig - jg < WIN_);
                p[m][n] = valid ? __expf(s[m][n] - mnew) : 0.0f;
                psum += p[m][n];
            }
#pragma unroll
            for (int off = 8; off > 0; off >>= 1)
                psum += __shfl_xor_sync(0xffffffffu, psum, off);
            lrow[m] = lrow[m] * escale[m] + psum;
            mrow[m] = mnew;
#pragma unroll
            for (int n = 0; n < 4; n++) o[m][n] *= escale[m];
        }

        __syncthreads();
#pragma unroll
        for (int m = 0; m < 4; m++)
            *reinterpret_cast<float4*>(&KPs[(i0 + m) * QS_STRIDE + j0]) =
                make_float4(p[m][0], p[m][1], p[m][2], p[m][3]);
        __syncthreads();

#pragma unroll 8
        for (int j = 0; j < 64; j++) {
            float ra[4];
#pragma unroll
            for (int m = 0; m < 4; m++) ra[m] = KPs[(i0 + m) * QS_STRIDE + j];
            const float4 rv = *reinterpret_cast<const float4*>(&Vs[j * 64 + j0]);
            const float rb[4] = {rv.x, rv.y, rv.z, rv.w};
#pragma unroll
            for (int m = 0; m < 4; m++)
#pragma unroll
                for (int n = 0; n < 4; n++) o[m][n] += ra[m] * rb[n];
        }
    }

#pragma unroll
    for (int m = 0; m < 4; m++) {
        const float inv = 1.0f / lrow[m];
        float* yp = y + ((size_t)b * T_ + qt * 64 + i0 + m) * C_ + h * HS_ + j0;
        *reinterpret_cast<float4*>(yp) =
            make_float4(o[m][0] * inv, o[m][1] * inv, o[m][2] * inv, o[m][3] * inv);
    }
}

// ---------------------------------------------------------------------------
extern "C" void kernel_launch(void* const* d_in, const int* in_sizes, int n_in,
                              void* d_out, int out_size)
{
    const float* x      = (const float*)d_in[0];
    const float* W_attn = (const float*)d_in[1];
    const float* W_proj = (const float*)d_in[2];
    float* out = (float*)d_out;

    float *qkv, *y;
    __nv_bfloat16 *xh, *xl, *yh, *yl, *wah, *wal, *wph, *wpl;
    cudaGetSymbolAddress((void**)&qkv, g_qkv);
    cudaGetSymbolAddress((void**)&y,   g_y);
    cudaGetSymbolAddress((void**)&xh,  g_xh);
    cudaGetSymbolAddress((void**)&xl,  g_xl);
    cudaGetSymbolAddress((void**)&yh,  g_yh);
    cudaGetSymbolAddress((void**)&yl,  g_yl);
    cudaGetSymbolAddress((void**)&wah, g_wah);
    cudaGetSymbolAddress((void**)&wal, g_wal);
    cudaGetSymbolAddress((void**)&wph, g_wph);
    cudaGetSymbolAddress((void**)&wpl, g_wpl);

    cudaFuncSetAttribute(gemm_mma, cudaFuncAttributeMaxDynamicSharedMemorySize,
                         GEMM_SMEM);
    cudaFuncSetAttribute(swa_kernel, cudaFuncAttributeMaxDynamicSharedMemorySize,
                         SWA_SMEM_BYTES);

    const int M = B_ * T_;   // 4096

    split_convert<<<(M * C_ / 2 + 255) / 256, 256>>>(x, xh, xl, M * C_ / 2);
    {
        dim3 g(3 * C_ / 32, C_ / 32);
        transpose_split<<<g, 256>>>(W_attn, wah, wal, C_, 3 * C_);
    }
    {
        dim3 g(C_ / 32, C_ / 32);
        transpose_split<<<g, 256>>>(W_proj, wph, wpl, C_, C_);
    }

    // qkv = x @ W_attn  (M=4096, N=3072, K=1024)
    {
        dim3 g(3 * C_ / BN, M / BM);
        gemm_mma<<<g, 256, GEMM_SMEM>>>(xh, xl, wah, wal, qkv, M, 3 * C_, C_);
    }

    // fused SWA -> y
    {
        dim3 g(T_ / 64, NH_, B_);
        swa_kernel<<<g, 256, SWA_SMEM_BYTES>>>(qkv, y);
    }

    // out = y @ W_proj  (M=4096, N=1024, K=1024)
    split_convert<<<(M * C_ / 2 + 255) / 256, 256>>>(y, yh, yl, M * C_ / 2);
    {
        dim3 g(C_ / BN, M / BM);
        gemm_mma<<<g, 256, GEMM_SMEM>>>(yh, yl, wph, wpl, out, M, C_, C_);
    }
}

// round 4
// speedup vs baseline: 3.8939x; 1.2389x over previous
#include <cuda_runtime.h>
#include <cuda_bf16.h>
#include <cstdint>
#include <math.h>

#define B_   2
#define T_   2048
#define C_   1024
#define NH_  16
#define HS_  64
#define WIN_ 256

// ---------------------------------------------------------------------------
// Scratch (__device__ globals; no allocation allowed)
// ---------------------------------------------------------------------------
__device__ float g_qkv[(size_t)B_ * T_ * 3 * C_];        // [B,T,3C] fp32
__device__ float g_y  [(size_t)B_ * T_ * C_];            // [B,T,C]  fp32
__device__ __nv_bfloat16 g_xh[(size_t)B_ * T_ * C_];
__device__ __nv_bfloat16 g_xl[(size_t)B_ * T_ * C_];
__device__ __nv_bfloat16 g_yh[(size_t)B_ * T_ * C_];
__device__ __nv_bfloat16 g_yl[(size_t)B_ * T_ * C_];
__device__ __nv_bfloat16 g_wah[(size_t)3 * C_ * C_];     // W_attn^T [3C, C]
__device__ __nv_bfloat16 g_wal[(size_t)3 * C_ * C_];
__device__ __nv_bfloat16 g_wph[(size_t)C_ * C_];         // W_proj^T [C, C]
__device__ __nv_bfloat16 g_wpl[(size_t)C_ * C_];

// ---------------------------------------------------------------------------
// mma.sync / ldmatrix / cp.async helpers (plain sm_80-level PTX)
// ---------------------------------------------------------------------------
__device__ __forceinline__ uint32_t smem_to_u32(const void* smem_ptr) {
    uint32_t addr;
    asm("{ .reg .u64 tmp; cvta.to.shared.u64 tmp, %1; cvt.u32.u64 %0, tmp; }"
        : "=r"(addr) : "l"(smem_ptr));
    return addr;
}
__device__ __forceinline__ void cp16(uint32_t saddr, const void* g) {
    asm volatile("cp.async.cg.shared.global [%0], [%1], 16;" :: "r"(saddr), "l"(g));
}
__device__ __forceinline__ void cp_commit() {
    asm volatile("cp.async.commit_group;" ::: "memory");
}
template <int N>
__device__ __forceinline__ void cp_wait() {
    asm volatile("cp.async.wait_group %0;" :: "n"(N) : "memory");
}
__device__ __forceinline__ void ldm4(uint32_t* r, uint32_t addr) {
    asm volatile("ldmatrix.sync.aligned.m8n8.x4.shared.b16 {%0,%1,%2,%3}, [%4];"
        : "=r"(r[0]), "=r"(r[1]), "=r"(r[2]), "=r"(r[3]) : "r"(addr));
}
__device__ __forceinline__ void ldm4t(uint32_t* r, uint32_t addr) {
    asm volatile("ldmatrix.sync.aligned.m8n8.x4.trans.shared.b16 {%0,%1,%2,%3}, [%4];"
        : "=r"(r[0]), "=r"(r[1]), "=r"(r[2]), "=r"(r[3]) : "r"(addr));
}
__device__ __forceinline__ void mma_bf16(float* c, const uint32_t* a, const uint32_t* b) {
    asm volatile("mma.sync.aligned.m16n8k16.row.col.f32.bf16.bf16.f32 "
        "{%0,%1,%2,%3}, {%4,%5,%6,%7}, {%8,%9}, {%0,%1,%2,%3};"
        : "+f"(c[0]), "+f"(c[1]), "+f"(c[2]), "+f"(c[3])
        : "r"(a[0]), "r"(a[1]), "r"(a[2]), "r"(a[3]), "r"(b[0]), "r"(b[1]));
}
__device__ __forceinline__ uint32_t pack_bf16(float lo, float hi) {
    __nv_bfloat162 t = __floats2bfloat162_rn(lo, hi);
    return *reinterpret_cast<uint32_t*>(&t);
}

// ---------------------------------------------------------------------------
// Split-precision conversion kernels
// ---------------------------------------------------------------------------
__global__ __launch_bounds__(256) void split_convert(const float* __restrict__ in,
                                                     __nv_bfloat16* __restrict__ oh,
                                                     __nv_bfloat16* __restrict__ ol,
                                                     int n2)
{
    int i = blockIdx.x * blockDim.x + threadIdx.x;
    if (i >= n2) return;
    float2 v = reinterpret_cast<const float2*>(in)[i];
    __nv_bfloat16 hx = __float2bfloat16(v.x);
    __nv_bfloat16 hy = __float2bfloat16(v.y);
    float rx = v.x - __bfloat162float(hx);
    float ry = v.y - __bfloat162float(hy);
    __nv_bfloat162 th; th.x = hx; th.y = hy;
    __nv_bfloat162 tl; tl.x = __float2bfloat16(rx); tl.y = __float2bfloat16(ry);
    reinterpret_cast<__nv_bfloat162*>(oh)[i] = th;
    reinterpret_cast<__nv_bfloat162*>(ol)[i] = tl;
}

// in: [K,N] fp32 row-major -> out hi/lo: [N,K] bf16 (transposed, K-major)
__global__ __launch_bounds__(256) void transpose_split(const float* __restrict__ in,
                                                       __nv_bfloat16* __restrict__ oh,
                                                       __nv_bfloat16* __restrict__ ol,
                                                       int K, int N)
{
    __shared__ float t[32][33];
    const int nt = blockIdx.x * 32;
    const int kt = blockIdx.y * 32;
    const int tx = threadIdx.x & 31;
    const int ty = threadIdx.x >> 5;     // 0..7
#pragma unroll
    for (int j = 0; j < 4; j++) {
        int k = kt + ty + j * 8;
        t[ty + j * 8][tx] = in[(size_t)k * N + nt + tx];
    }
    __syncthreads();
#pragma unroll
    for (int j = 0; j < 4; j++) {
        int n = nt + ty + j * 8;
        int k = kt + tx;
        float v = t[tx][ty + j * 8];
        __nv_bfloat16 h = __float2bfloat16(v);
        oh[(size_t)n * K + k] = h;
        ol[(size_t)n * K + k] = __float2bfloat16(v - __bfloat162float(h));
    }
}

// ---------------------------------------------------------------------------
// Split-bf16 GEMM via mma.sync (HMMA) — unchanged from round 3 (proven).
// ---------------------------------------------------------------------------
#define BM 128
#define BN 128
#define BKC 32
#define LDA 40
#define TILE_BYTES (128 * LDA * 2)
#define OFF_AH 0
#define OFF_AL (TILE_BYTES)
#define OFF_BH (2 * TILE_BYTES)
#define OFF_BL (3 * TILE_BYTES)
#define STAGE_BYTES (4 * TILE_BYTES)
#define GEMM_SMEM (2 * STAGE_BYTES)

__global__ __launch_bounds__(256) void gemm_mma(const __nv_bfloat16* __restrict__ Ah,
                                                const __nv_bfloat16* __restrict__ Al,
                                                const __nv_bfloat16* __restrict__ Bh,
                                                const __nv_bfloat16* __restrict__ Bl,
                                                float* __restrict__ C,
                                                int M, int N, int K)
{
    extern __shared__ char smem[];
    const uint32_t sbase = smem_to_u32(smem);

    const int tid  = threadIdx.x;
    const int lane = tid & 31;
    const int wid  = tid >> 5;
    const int warpRow = wid & 1;
    const int warpCol = wid >> 1;
    const int m0 = blockIdx.y * BM;
    const int n0 = blockIdx.x * BN;
    const int NC = K / BKC;

    const int v0 = tid, v1 = tid + 256;
    const int r0 = v0 >> 2, s0 = v0 & 3;
    const int r1 = v1 >> 2, s1 = v1 & 3;
    const uint32_t so0 = (uint32_t)(r0 * LDA + s0 * 8) * 2;
    const uint32_t so1 = (uint32_t)(r1 * LDA + s1 * 8) * 2;

    float acc[4][4][4];
#pragma unroll
    for (int mt = 0; mt < 4; mt++)
#pragma unroll
        for (int nt = 0; nt < 4; nt++)
#pragma unroll
            for (int e = 0; e < 4; e++) acc[mt][nt][e] = 0.0f;

    const uint32_t a_row = (uint32_t)(warpRow * 64 + (lane & 15));
    const uint32_t a_kof = (uint32_t)((lane >> 4) << 3);
    const uint32_t b_row = (uint32_t)(warpCol * 32 + (lane & 7) + ((lane & 16) >> 1));
    const uint32_t b_kof = (uint32_t)(lane & 8);

    auto load_stage = [&](int stg, int kk) {
        const uint32_t sb = sbase + stg * STAGE_BYTES;
        const size_t ga0 = (size_t)(m0 + r0) * K + kk + s0 * 8;
        const size_t ga1 = (size_t)(m0 + r1) * K + kk + s1 * 8;
        const size_t gb0 = (size_t)(n0 + r0) * K + kk + s0 * 8;
        const size_t gb1 = (size_t)(n0 + r1) * K + kk + s1 * 8;
        cp16(sb + OFF_AH + so0, Ah + ga0);
        cp16(sb + OFF_AH + so1, Ah + ga1);
        cp16(sb + OFF_AL + so0, Al + ga0);
        cp16(sb + OFF_AL + so1, Al + ga1);
        cp16(sb + OFF_BH + so0, Bh + gb0);
        cp16(sb + OFF_BH + so1, Bh + gb1);
        cp16(sb + OFF_BL + so0, Bl + gb0);
        cp16(sb + OFF_BL + so1, Bl + gb1);
        cp_commit();
    };

    load_stage(0, 0);

    for (int c = 0; c < NC; c++) {
        const int buf = c & 1;
        if (c + 1 < NC) {
            load_stage(buf ^ 1, (c + 1) * BKC);
            cp_wait<1>();
        } else {
            cp_wait<0>();
        }
        __syncthreads();

        const uint32_t sb = sbase + buf * STAGE_BYTES;

#pragma unroll
        for (int ks = 0; ks < 2; ks++) {
            const uint32_t akc = (uint32_t)(ks * 16) + a_kof;
            const uint32_t bkc = (uint32_t)(ks * 16) + b_kof;

            uint32_t fAh[4][4], fAl[4][4];
#pragma unroll
            for (int mt = 0; mt < 4; mt++) {
                const uint32_t off = ((a_row + mt * 16) * LDA + akc) * 2;
                ldm4(fAh[mt], sb + OFF_AH + off);
                ldm4(fAl[mt], sb + OFF_AL + off);
            }
            uint32_t fBh[2][4], fBl[2][4];
#pragma unroll
            for (int g = 0; g < 2; g++) {
                const uint32_t off = ((b_row + g * 16) * LDA + bkc) * 2;
                ldm4(fBh[g], sb + OFF_BH + off);
                ldm4(fBl[g], sb + OFF_BL + off);
            }

#pragma unroll
            for (int mt = 0; mt < 4; mt++) {
#pragma unroll
                for (int nt = 0; nt < 4; nt++) {
                    const uint32_t* bh = &fBh[nt >> 1][(nt & 1) * 2];
                    const uint32_t* bl = &fBl[nt >> 1][(nt & 1) * 2];
                    mma_bf16(acc[mt][nt], fAh[mt], bh);
                    mma_bf16(acc[mt][nt], fAh[mt], bl);
                    mma_bf16(acc[mt][nt], fAl[mt], bh);
                }
            }
        }
        __syncthreads();
    }

    const int erow = m0 + warpRow * 64 + (lane >> 2);
    const int ecol = n0 + warpCol * 32 + (lane & 3) * 2;
#pragma unroll
    for (int mt = 0; mt < 4; mt++) {
#pragma unroll
        for (int nt = 0; nt < 4; nt++) {
            float* p0 = C + (size_t)(erow + mt * 16) * N + ecol + nt * 8;
            float* p1 = C + (size_t)(erow + mt * 16 + 8) * N + ecol + nt * 8;
            *reinterpret_cast<float2*>(p0) = make_float2(acc[mt][nt][0], acc[mt][nt][1]);
            *reinterpret_cast<float2*>(p1) = make_float2(acc[mt][nt][2], acc[mt][nt][3]);
        }
    }
}

// ---------------------------------------------------------------------------
// Tensor-core sliding-window flash attention (split-bf16, 3-product).
// 1 CTA = (b, h, 64-query tile), 4 warps; warp w owns S/O rows [16w,16w+16).
// Q/K/V staged in smem as bf16 hi/lo tiles, row stride 72 (conflict-free ldmatrix).
// S via Q(A-frag) x K(B-frag, natural [j][d]); softmax in registers;
// P (hi/lo, register A-frags) x V (B-frag via ldmatrix.trans on natural [j][d]).
// ---------------------------------------------------------------------------
#define SWA_LDT 72
#define SWA_TILE_B (64 * SWA_LDT * 2)     // 9216 bytes per tile
#define SWA_SMEM (6 * SWA_TILE_B)         // 55296

__global__ __launch_bounds__(128, 3) void swa_mma(const float* __restrict__ qkv,
                                                  float* __restrict__ y)
{
    extern __shared__ char sm[];
    const uint32_t sb = smem_to_u32(sm);
    const uint32_t QH = sb;
    const uint32_t QL = sb + 1 * SWA_TILE_B;
    const uint32_t KH = sb + 2 * SWA_TILE_B;
    const uint32_t KL = sb + 3 * SWA_TILE_B;
    const uint32_t VH = sb + 4 * SWA_TILE_B;
    const uint32_t VL = sb + 5 * SWA_TILE_B;

    const int qt   = blockIdx.x;
    const int h    = blockIdx.y;
    const int b    = blockIdx.z;
    const int tid  = threadIdx.x;
    const int lane = tid & 31;
    const int w    = tid >> 5;

    const size_t st = 3 * C_;
    const float* base = qkv + (size_t)b * T_ * st + (size_t)h * HS_;

    // --- load Q tile (64x64 fp32 -> split bf16 hi/lo in smem) ---
    for (int it = tid; it < 1024; it += 128) {
        const int r  = it >> 4;
        const int d0 = (it & 15) * 4;
        const float4 v = *reinterpret_cast<const float4*>(
            base + (size_t)(qt * 64 + r) * st + d0);
        __nv_bfloat16 h0 = __float2bfloat16(v.x), h1 = __float2bfloat16(v.y);
        __nv_bfloat16 h2 = __float2bfloat16(v.z), h3 = __float2bfloat16(v.w);
        uint2 hi, lo;
        hi.x = pack_bf16(__bfloat162float(h0), __bfloat162float(h1));
        hi.y = pack_bf16(__bfloat162float(h2), __bfloat162float(h3));
        lo.x = pack_bf16(v.x - __bfloat162float(h0), v.y - __bfloat162float(h1));
        lo.y = pack_bf16(v.z - __bfloat162float(h2), v.w - __bfloat162float(h3));
        const uint32_t off = (uint32_t)(r * SWA_LDT + d0) * 2;
        *reinterpret_cast<uint2*>(sm + (QH - sb) + off) = hi;
        *reinterpret_cast<uint2*>(sm + (QL - sb) + off) = lo;
    }

    float o[8][4];
#pragma unroll
    for (int nt = 0; nt < 8; nt++)
#pragma unroll
        for (int e = 0; e < 4; e++) o[nt][e] = 0.0f;
    float mrow[2] = {-1e30f, -1e30f};
    float lrow[2] = {0.0f, 0.0f};

    const int ig0 = qt * 64 + w * 16 + (lane >> 2);   // row of elems 0,1
    const int ig1 = ig0 + 8;                          // row of elems 2,3

    const int lo_q   = qt * 64 - (WIN_ - 1);
    const int kt_lo  = lo_q > 0 ? (lo_q >> 6) : 0;

    for (int kt = kt_lo; kt <= qt; kt++) {
        __syncthreads();   // prior-iter V reads done before overwrite (also Q stores, 1st iter)
        // --- load K & V tiles ---
        for (int it = tid; it < 1024; it += 128) {
            const int r  = it >> 4;
            const int d0 = (it & 15) * 4;
            const float* kp = base + C_ + (size_t)(kt * 64 + r) * st + d0;
            const float4 kv = *reinterpret_cast<const float4*>(kp);
            const float4 vv = *reinterpret_cast<const float4*>(kp + C_);
            const uint32_t off = (uint32_t)(r * SWA_LDT + d0) * 2;
            {
                __nv_bfloat16 h0 = __float2bfloat16(kv.x), h1 = __float2bfloat16(kv.y);
                __nv_bfloat16 h2 = __float2bfloat16(kv.z), h3 = __float2bfloat16(kv.w);
                uint2 hi, lo;
                hi.x = pack_bf16(__bfloat162float(h0), __bfloat162float(h1));
                hi.y = pack_bf16(__bfloat162float(h2), __bfloat162float(h3));
                lo.x = pack_bf16(kv.x - __bfloat162float(h0), kv.y - __bfloat162float(h1));
                lo.y = pack_bf16(kv.z - __bfloat162float(h2), kv.w - __bfloat162float(h3));
                *reinterpret_cast<uint2*>(sm + (KH - sb) + off) = hi;
                *reinterpret_cast<uint2*>(sm + (KL - sb) + off) = lo;
            }
            {
                __nv_bfloat16 h0 = __float2bfloat16(vv.x), h1 = __float2bfloat16(vv.y);
                __nv_bfloat16 h2 = __float2bfloat16(vv.z), h3 = __float2bfloat16(vv.w);
                uint2 hi, lo;
                hi.x = pack_bf16(__bfloat162float(h0), __bfloat162float(h1));
                hi.y = pack_bf16(__bfloat162float(h2), __bfloat162float(h3));
                lo.x = pack_bf16(vv.x - __bfloat162float(h0), vv.y - __bfloat162float(h1));
                lo.y = pack_bf16(vv.z - __bfloat162float(h2), vv.w - __bfloat162float(h3));
                *reinterpret_cast<uint2*>(sm + (VH - sb) + off) = hi;
                *reinterpret_cast<uint2*>(sm + (VL - sb) + off) = lo;
            }
        }
        __syncthreads();

        // --- S = Q @ K^T (split 3-product) ---
        float s[8][4];
#pragma unroll
        for (int nt = 0; nt < 8; nt++)
#pragma unroll
            for (int e = 0; e < 4; e++) s[nt][e] = 0.0f;

#pragma unroll
        for (int ks = 0; ks < 4; ks++) {
            uint32_t qh[4], ql[4];
            const uint32_t aoff =
                (uint32_t)((w * 16 + (lane & 15)) * SWA_LDT + ks * 16 + ((lane >> 4) << 3)) * 2;
            ldm4(qh, QH + aoff);
            ldm4(ql, QL + aoff);
#pragma unroll
            for (int jc = 0; jc < 4; jc++) {
                uint32_t kh[4], kl[4];
                const uint32_t boff =
                    (uint32_t)((jc * 16 + (lane & 7) + ((lane & 16) >> 1)) * SWA_LDT
                               + ks * 16 + (lane & 8)) * 2;
                ldm4(kh, KH + boff);
                ldm4(kl, KL + boff);
                mma_bf16(s[jc * 2],     qh, kh);
                mma_bf16(s[jc * 2],     qh, kl);
                mma_bf16(s[jc * 2],     ql, kh);
                mma_bf16(s[jc * 2 + 1], qh, kh + 2);
                mma_bf16(s[jc * 2 + 1], qh, kl + 2);
                mma_bf16(s[jc * 2 + 1], ql, kh + 2);
            }
        }

        // --- masked online softmax (registers only) ---
        const float sc = 0.125f;
        const int jb = kt * 64 + 2 * (lane & 3);
        float tmax0 = -1e30f, tmax1 = -1e30f;
#pragma unroll
        for (int nt = 0; nt < 8; nt++) {
            const int j0 = jb + nt * 8, j1 = j0 + 1;
            const bool v00 = (j0 <= ig0) && (ig0 - j0 < WIN_);
            const bool v01 = (j1 <= ig0) && (ig0 - j1 < WIN_);
            const bool v10 = (j0 <= ig1) && (ig1 - j0 < WIN_);
            const bool v11 = (j1 <= ig1) && (ig1 - j1 < WIN_);
            s[nt][0] *= sc; s[nt][1] *= sc; s[nt][2] *= sc; s[nt][3] *= sc;
            if (v00) tmax0 = fmaxf(tmax0, s[nt][0]);
            if (v01) tmax0 = fmaxf(tmax0, s[nt][1]);
            if (v10) tmax1 = fmaxf(tmax1, s[nt][2]);
            if (v11) tmax1 = fmaxf(tmax1, s[nt][3]);
        }
        tmax0 = fmaxf(tmax0, __shfl_xor_sync(0xffffffffu, tmax0, 1));
        tmax0 = fmaxf(tmax0, __shfl_xor_sync(0xffffffffu, tmax0, 2));
        tmax1 = fmaxf(tmax1, __shfl_xor_sync(0xffffffffu, tmax1, 1));
        tmax1 = fmaxf(tmax1, __shfl_xor_sync(0xffffffffu, tmax1, 2));

        const float mn0 = fmaxf(mrow[0], tmax0);
        const float mn1 = fmaxf(mrow[1], tmax1);
        const float es0 = __expf(mrow[0] - mn0);
        const float es1 = __expf(mrow[1] - mn1);
        mrow[0] = mn0; mrow[1] = mn1;

        uint32_t ph01[8], ph23[8], pl01[8], pl23[8];
        float ps0 = 0.0f, ps1 = 0.0f;
#pragma unroll
        for (int nt = 0; nt < 8; nt++) {
            const int j0 = jb + nt * 8, j1 = j0 + 1;
            const bool v00 = (j0 <= ig0) && (ig0 - j0 < WIN_);
            const bool v01 = (j1 <= ig0) && (ig0 - j1 < WIN_);
            const bool v10 = (j0 <= ig1) && (ig1 - j0 < WIN_);
            const bool v11 = (j1 <= ig1) && (ig1 - j1 < WIN_);
            const float p00 = v00 ? __expf(s[nt][0] - mn0) : 0.0f;
            const float p01 = v01 ? __expf(s[nt][1] - mn0) : 0.0f;
            const float p10 = v10 ? __expf(s[nt][2] - mn1) : 0.0f;
            const float p11 = v11 ? __expf(s[nt][3] - mn1) : 0.0f;
            ps0 += p00 + p01;
            ps1 += p10 + p11;
            __nv_bfloat162 h01 = __floats2bfloat162_rn(p00, p01);
            __nv_bfloat162 h23 = __floats2bfloat162_rn(p10, p11);
            ph01[nt] = *reinterpret_cast<uint32_t*>(&h01);
            ph23[nt] = *reinterpret_cast<uint32_t*>(&h23);
            pl01[nt] = pack_bf16(p00 - __bfloat162float(h01.x),
                                 p01 - __bfloat162float(h01.y));
            pl23[nt] = pack_bf16(p10 - __bfloat162float(h23.x),
                                 p11 - __bfloat162float(h23.y));
        }
        ps0 += __shfl_xor_sync(0xffffffffu, ps0, 1);
        ps0 += __shfl_xor_sync(0xffffffffu, ps0, 2);
        ps1 += __shfl_xor_sync(0xffffffffu, ps1, 1);
        ps1 += __shfl_xor_sync(0xffffffffu, ps1, 2);
        lrow[0] = lrow[0] * es0 + ps0;
        lrow[1] = lrow[1] * es1 + ps1;
#pragma unroll
        for (int nt = 0; nt < 8; nt++) {
            o[nt][0] *= es0; o[nt][1] *= es0;
            o[nt][2] *= es1; o[nt][3] *= es1;
        }

        // --- O += P @ V (P hi/lo in registers; V via ldmatrix.trans) ---
#pragma unroll
        for (int kj = 0; kj < 4; kj++) {
            uint32_t ah[4] = {ph01[2 * kj], ph23[2 * kj], ph01[2 * kj + 1], ph23[2 * kj + 1]};
            uint32_t al[4] = {pl01[2 * kj], pl23[2 * kj], pl01[2 * kj + 1], pl23[2 * kj + 1]};
#pragma unroll
            for (int dc = 0; dc < 4; dc++) {
                uint32_t vh[4], vl[4];
                const uint32_t voff =
                    (uint32_t)((kj * 16 + (lane & 15)) * SWA_LDT
                               + dc * 16 + ((lane >> 4) << 3)) * 2;
                ldm4t(vh, VH + voff);
                ldm4t(vl, VL + voff);
                mma_bf16(o[dc * 2],     ah, vh);
                mma_bf16(o[dc * 2],     ah, vl);
                mma_bf16(o[dc * 2],     al, vh);
                mma_bf16(o[dc * 2 + 1], ah, vh + 2);
                mma_bf16(o[dc * 2 + 1], ah, vl + 2);
                mma_bf16(o[dc * 2 + 1], al, vh + 2);
            }
        }
    }

    // --- normalize + write y[b, i, h*64+d] ---
    const float inv0 = 1.0f / lrow[0];
    const float inv1 = 1.0f / lrow[1];
    const size_t row0 = (size_t)b * T_ + qt * 64 + w * 16 + (lane >> 2);
    const int    colb = h * HS_ + 2 * (lane & 3);
#pragma unroll
    for (int nt = 0; nt < 8; nt++) {
        float* p0 = y + row0 * C_ + colb + nt * 8;
        float* p1 = y + (row0 + 8) * C_ + colb + nt * 8;
        *reinterpret_cast<float2*>(p0) = make_float2(o[nt][0] * inv0, o[nt][1] * inv0);
        *reinterpret_cast<float2*>(p1) = make_float2(o[nt][2] * inv1, o[nt][3] * inv1);
    }
}

// ---------------------------------------------------------------------------
extern "C" void kernel_launch(void* const* d_in, const int* in_sizes, int n_in,
                              void* d_out, int out_size)
{
    const float* x      = (const float*)d_in[0];
    const float* W_attn = (const float*)d_in[1];
    const float* W_proj = (const float*)d_in[2];
    float* out = (float*)d_out;

    float *qkv, *y;
    __nv_bfloat16 *xh, *xl, *yh, *yl, *wah, *wal, *wph, *wpl;
    cudaGetSymbolAddress((void**)&qkv, g_qkv);
    cudaGetSymbolAddress((void**)&y,   g_y);
    cudaGetSymbolAddress((void**)&xh,  g_xh);
    cudaGetSymbolAddress((void**)&xl,  g_xl);
    cudaGetSymbolAddress((void**)&yh,  g_yh);
    cudaGetSymbolAddress((void**)&yl,  g_yl);
    cudaGetSymbolAddress((void**)&wah, g_wah);
    cudaGetSymbolAddress((void**)&wal, g_wal);
    cudaGetSymbolAddress((void**)&wph, g_wph);
    cudaGetSymbolAddress((void**)&wpl, g_wpl);

    cudaFuncSetAttribute(gemm_mma, cudaFuncAttributeMaxDynamicSharedMemorySize,
                         GEMM_SMEM);
    cudaFuncSetAttribute(swa_mma, cudaFuncAttributeMaxDynamicSharedMemorySize,
                         SWA_SMEM);

    const int M = B_ * T_;   // 4096

    split_convert<<<(M * C_ / 2 + 255) / 256, 256>>>(x, xh, xl, M * C_ / 2);
    {
        dim3 g(3 * C_ / 32, C_ / 32);
        transpose_split<<<g, 256>>>(W_attn, wah, wal, C_, 3 * C_);
    }
    {
        dim3 g(C_ / 32, C_ / 32);
        transpose_split<<<g, 256>>>(W_proj, wph, wpl, C_, C_);
    }

    // qkv = x @ W_attn  (M=4096, N=3072, K=1024)
    {
        dim3 g(3 * C_ / BN, M / BM);
        gemm_mma<<<g, 256, GEMM_SMEM>>>(xh, xl, wah, wal, qkv, M, 3 * C_, C_);
    }

    // fused SWA -> y (tensor cores)
    {
        dim3 g(T_ / 64, NH_, B_);
        swa_mma<<<g, 128, SWA_SMEM>>>(qkv, y);
    }

    // out = y @ W_proj  (M=4096, N=1024, K=1024)
    split_convert<<<(M * C_ / 2 + 255) / 256, 256>>>(y, yh, yl, M * C_ / 2);
    {
        dim3 g(C_ / BN, M / BM);
        gemm_mma<<<g, 256, GEMM_SMEM>>>(yh, yl, wph, wpl, out, M, C_, C_);
    }
}